// round 1
// baseline (speedup 1.0000x reference)
#include <cuda_runtime.h>
#include <math.h>

// Problem dims (fixed)
#define NB 8
#define TT 8
#define LLEN 257
#define HH 16
#define CC 64
#define DD 1024
#define QQ 256
#define MROWS (NB*QQ)   // 2048

// ---------------- scratch (static device arrays; no allocation) ----------------
__device__ float g_ln  [MROWS*DD];      // LN outputs (syno ln)
__device__ float g_h1  [MROWS*(DD/8)];  // adaptor hidden
__device__ float g_sadj[MROWS*DD];      // _s = s + adaptor(s)
__device__ float g_x   [MROWS*DD];      // ln1 / ln2 output (reused)
__device__ float g_sq  [MROWS*DD];      // scaled query
__device__ float g_mix [MROWS*DD];      // attention+conv+mean output
__device__ float g_s1  [MROWS*DD];      // first residual sum
__device__ float g_hmid[MROWS*4*DD];    // MLP hidden
__device__ float g_tek [TT*DD];
__device__ float g_tev [TT*DD];

// ---------------- row LayerNorm: (rows,1024) -> (rows,1024) ----------------
__global__ __launch_bounds__(256)
void ln_rows_k(const float* __restrict__ in, const float* __restrict__ w,
               const float* __restrict__ b, float* __restrict__ out)
{
    __shared__ float red[18];
    int r = blockIdx.x;
    int tid = threadIdx.x;
    int lane = tid & 31, warp = tid >> 5;
    float4 v = reinterpret_cast<const float4*>(in + (size_t)r*DD)[tid];
    float s = v.x + v.y + v.z + v.w;
    float q = v.x*v.x + v.y*v.y + v.z*v.z + v.w*v.w;
    #pragma unroll
    for (int o = 16; o; o >>= 1) {
        s += __shfl_xor_sync(0xffffffffu, s, o);
        q += __shfl_xor_sync(0xffffffffu, q, o);
    }
    if (lane == 0) { red[warp] = s; red[8+warp] = q; }
    __syncthreads();
    if (tid == 0) {
        float ss = 0.f, qs = 0.f;
        #pragma unroll
        for (int i = 0; i < 8; i++) { ss += red[i]; qs += red[8+i]; }
        red[16] = ss * (1.f/DD);
        red[17] = qs * (1.f/DD);
    }
    __syncthreads();
    float mean = red[16];
    float var  = red[17] - mean*mean;
    float rs   = rsqrtf(var + 1e-5f);
    float4 wv = reinterpret_cast<const float4*>(w)[tid];
    float4 bv = reinterpret_cast<const float4*>(b)[tid];
    float4 o4;
    o4.x = (v.x-mean)*rs*wv.x + bv.x;
    o4.y = (v.y-mean)*rs*wv.y + bv.y;
    o4.z = (v.z-mean)*rs*wv.z + bv.z;
    o4.w = (v.w-mean)*rs*wv.w + bv.w;
    reinterpret_cast<float4*>(out + (size_t)r*DD)[tid] = o4;
}

// ---------------- SGEMM: C(M,N) = A(M,K) @ W(N,K)^T (+bias) (+epilogue) ----------------
// EPI: 0 = bias only, 1 = (x+bias)*scale, 2 = x+bias+res, 3 = quick_gelu(x+bias)
template<int EPI>
__global__ __launch_bounds__(256)
void sgemm_nt(const float* __restrict__ A, const float* __restrict__ W,
              const float* __restrict__ bias, const float* __restrict__ res,
              float* __restrict__ C, int M, int N, int K, float scale)
{
    __shared__ float As[2][16][132];
    __shared__ float Ws[2][16][132];
    int tid = threadIdx.x;
    int m0 = blockIdx.y * 128, n0 = blockIdx.x * 128;
    int tx = tid & 15, ty = tid >> 4;
    int row0 = tid >> 2;          // 0..63
    int row1 = row0 + 64;
    int k4   = (tid & 3) * 4;

    const float* Ap0 = A + (size_t)(m0+row0)*K + k4;
    const float* Ap1 = A + (size_t)(m0+row1)*K + k4;
    const float* Wp0 = W + (size_t)(n0+row0)*K + k4;
    const float* Wp1 = W + (size_t)(n0+row1)*K + k4;

    float4 pa0 = *(const float4*)Ap0;
    float4 pa1 = *(const float4*)Ap1;
    float4 pw0 = *(const float4*)Wp0;
    float4 pw1 = *(const float4*)Wp1;

    int buf = 0;
    As[0][k4+0][row0]=pa0.x; As[0][k4+1][row0]=pa0.y; As[0][k4+2][row0]=pa0.z; As[0][k4+3][row0]=pa0.w;
    As[0][k4+0][row1]=pa1.x; As[0][k4+1][row1]=pa1.y; As[0][k4+2][row1]=pa1.z; As[0][k4+3][row1]=pa1.w;
    Ws[0][k4+0][row0]=pw0.x; Ws[0][k4+1][row0]=pw0.y; Ws[0][k4+2][row0]=pw0.z; Ws[0][k4+3][row0]=pw0.w;
    Ws[0][k4+0][row1]=pw1.x; Ws[0][k4+1][row1]=pw1.y; Ws[0][k4+2][row1]=pw1.z; Ws[0][k4+3][row1]=pw1.w;
    __syncthreads();

    float acc[8][8];
    #pragma unroll
    for (int i = 0; i < 8; i++)
        #pragma unroll
        for (int j = 0; j < 8; j++) acc[i][j] = 0.f;

    int nT = K / 16;
    for (int t = 0; t < nT; t++) {
        if (t + 1 < nT) {
            int off = (t+1)*16;
            pa0 = *(const float4*)(Ap0 + off);
            pa1 = *(const float4*)(Ap1 + off);
            pw0 = *(const float4*)(Wp0 + off);
            pw1 = *(const float4*)(Wp1 + off);
        }
        #pragma unroll
        for (int kk = 0; kk < 16; kk++) {
            float4 a0 = *(float4*)&As[buf][kk][ty*8];
            float4 a1 = *(float4*)&As[buf][kk][ty*8+4];
            float4 b0 = *(float4*)&Ws[buf][kk][tx*8];
            float4 b1 = *(float4*)&Ws[buf][kk][tx*8+4];
            float av[8] = {a0.x,a0.y,a0.z,a0.w,a1.x,a1.y,a1.z,a1.w};
            float bv[8] = {b0.x,b0.y,b0.z,b0.w,b1.x,b1.y,b1.z,b1.w};
            #pragma unroll
            for (int i = 0; i < 8; i++)
                #pragma unroll
                for (int j = 0; j < 8; j++)
                    acc[i][j] += av[i]*bv[j];
        }
        if (t + 1 < nT) {
            buf ^= 1;
            As[buf][k4+0][row0]=pa0.x; As[buf][k4+1][row0]=pa0.y; As[buf][k4+2][row0]=pa0.z; As[buf][k4+3][row0]=pa0.w;
            As[buf][k4+0][row1]=pa1.x; As[buf][k4+1][row1]=pa1.y; As[buf][k4+2][row1]=pa1.z; As[buf][k4+3][row1]=pa1.w;
            Ws[buf][k4+0][row0]=pw0.x; Ws[buf][k4+1][row0]=pw0.y; Ws[buf][k4+2][row0]=pw0.z; Ws[buf][k4+3][row0]=pw0.w;
            Ws[buf][k4+0][row1]=pw1.x; Ws[buf][k4+1][row1]=pw1.y; Ws[buf][k4+2][row1]=pw1.z; Ws[buf][k4+3][row1]=pw1.w;
            __syncthreads();
        }
    }

    #pragma unroll
    for (int i = 0; i < 8; i++) {
        int m = m0 + ty*8 + i;
        float* Crow = C + (size_t)m*N + n0 + tx*8;
        const float* Rrow = (EPI == 2) ? (res + (size_t)m*N + n0 + tx*8) : (const float*)0;
        #pragma unroll
        for (int j = 0; j < 8; j++) {
            float v = acc[i][j];
            if (bias) v += bias[n0 + tx*8 + j];
            if (EPI == 1) v *= scale;
            else if (EPI == 2) v += Rrow[j];
            else if (EPI == 3) v = v / (1.f + __expf(-1.702f * v));
            Crow[j] = v;
        }
    }
}

// ---------------- te path: _te = adaptor(te)+te ; te_k/te_v = (_te @ ipw[D:3D]^T + b) ----------------
__global__ __launch_bounds__(256)
void te_kernel(const float* __restrict__ te,
               const float* __restrict__ lnw, const float* __restrict__ lnb,
               const float* __restrict__ l1,  const float* __restrict__ l2,
               const float* __restrict__ ipw, const float* __restrict__ ipb,
               float* __restrict__ tek, float* __restrict__ tev)
{
    __shared__ float row[DD];
    __shared__ float lnr[DD];
    __shared__ float hb[256];
    __shared__ float hs[128];
    __shared__ float red[18];
    int t = blockIdx.x, tid = threadIdx.x;
    int lane = tid & 31, warp = tid >> 5;

    float4 v = reinterpret_cast<const float4*>(te + (size_t)t*DD)[tid];
    reinterpret_cast<float4*>(row)[tid] = v;
    float s = v.x+v.y+v.z+v.w;
    float q = v.x*v.x+v.y*v.y+v.z*v.z+v.w*v.w;
    #pragma unroll
    for (int o = 16; o; o >>= 1) {
        s += __shfl_xor_sync(0xffffffffu, s, o);
        q += __shfl_xor_sync(0xffffffffu, q, o);
    }
    if (lane == 0) { red[warp] = s; red[8+warp] = q; }
    __syncthreads();
    if (tid == 0) {
        float ss=0.f, qs=0.f;
        #pragma unroll
        for (int i=0;i<8;i++){ ss+=red[i]; qs+=red[8+i]; }
        red[16]=ss*(1.f/DD); red[17]=qs*(1.f/DD);
    }
    __syncthreads();
    float mean = red[16];
    float rs   = rsqrtf(red[17] - mean*mean + 1e-5f);
    float4 wv = reinterpret_cast<const float4*>(lnw)[tid];
    float4 bv = reinterpret_cast<const float4*>(lnb)[tid];
    float4 o4;
    o4.x=(v.x-mean)*rs*wv.x+bv.x; o4.y=(v.y-mean)*rs*wv.y+bv.y;
    o4.z=(v.z-mean)*rs*wv.z+bv.z; o4.w=(v.w-mean)*rs*wv.w+bv.w;
    reinterpret_cast<float4*>(lnr)[tid] = o4;
    __syncthreads();

    // h = LN(te) @ l1^T  (128 outputs, split each dot across 2 threads)
    {
        int j = tid & 127, half = tid >> 7;
        const float4* wr = (const float4*)(l1 + (size_t)j*DD + half*512);
        const float4* xr = (const float4*)(lnr + half*512);
        float p = 0.f;
        #pragma unroll 8
        for (int k = 0; k < 128; k++) {
            float4 w4 = wr[k]; float4 x4 = xr[k];
            p += w4.x*x4.x + w4.y*x4.y + w4.z*x4.z + w4.w*x4.w;
        }
        hb[tid] = p;
    }
    __syncthreads();
    if (tid < 128) hs[tid] = hb[tid] + hb[tid+128];
    __syncthreads();

    // _te = te + h @ l2^T
    float outv[4];
    #pragma unroll
    for (int ii = 0; ii < 4; ii++) {
        int i = tid + ii*256;
        const float* w2r = l2 + (size_t)i*128;
        float p = 0.f;
        #pragma unroll 8
        for (int j = 0; j < 128; j++) p += hs[j]*w2r[j];
        outv[ii] = row[i] + p;
    }
    __syncthreads();
    #pragma unroll
    for (int ii = 0; ii < 4; ii++) lnr[tid + ii*256] = outv[ii];
    __syncthreads();

    // te_k / te_v: rows D..3D of in_proj
    for (int o = tid; o < 2*DD; o += 256) {
        const float4* wr = (const float4*)(ipw + (size_t)(DD+o)*DD);
        float p = ipb[DD + o];
        #pragma unroll 8
        for (int d4 = 0; d4 < 256; d4++) {
            float4 w4 = wr[d4];
            float4 x4 = ((float4*)lnr)[d4];
            p += w4.x*x4.x + w4.y*x4.y + w4.z*x4.z + w4.w*x4.w;
        }
        if (o < DD) tek[(size_t)t*DD + o] = p;
        else        tev[(size_t)t*DD + (o-DD)] = p;
    }
}

// ---------------- attention + depthwise conv-over-t + mean-over-t (fused) ----------------
// grid (H, N), 256 threads. Per CTA: all Q rows for one (n,h), loop t, accumulate coef(t)*mix_t.
__global__ __launch_bounds__(256, 1)
void att_kernel(const float* __restrict__ sq, const float* __restrict__ ak,
                const float* __restrict__ av, const float* __restrict__ tek,
                const float* __restrict__ tev, const float* __restrict__ pm,
                const float* __restrict__ tw, const float* __restrict__ tb,
                float* __restrict__ outp)
{
    extern __shared__ float sm[];
    float* sq_s = sm;               // 256*64
    float* Ks   = sm + 16384;       // 256*65 (pitch 65: conflict-free lane-strided reads)
    float* Vs   = Ks + 16640;       // 256*64
    float* affs = Vs + 16384;       // 8 warps * 4 q * 256 k

    int h = blockIdx.x, n = blockIdx.y;
    int tid = threadIdx.x, warp = tid >> 5, lane = tid & 31;

    // load scaled-Q tile (256 q x 64 c)
    for (int idx = tid; idx < QQ*16; idx += 256) {
        int qr = idx >> 4, c4 = (idx & 15) * 4;
        *(float4*)&sq_s[qr*64 + c4] =
            *(const float4*)(sq + (size_t)(n*QQ+qr)*DD + h*64 + c4);
    }

    int c0 = lane*2;
    int d0 = h*64 + c0;
    float w0a = tw[d0*3+0],     w1a = tw[d0*3+1],     w2a = tw[d0*3+2];
    float w0b = tw[(d0+1)*3+0], w1b = tw[(d0+1)*3+1], w2b = tw[(d0+1)*3+2];
    float sa = 1.f + w0a + w1a + w2a;
    float sb = 1.f + w0b + w1b + w2b;

    float acc[32][2];
    #pragma unroll
    for (int i = 0; i < 32; i++) { acc[i][0] = 0.f; acc[i][1] = 0.f; }

    for (int t = 0; t < TT; t++) {
        __syncthreads();
        const float* kb  = ak  + ((size_t)(n*TT+t)*LLEN + 1)*DD + h*64;
        const float* vb  = av  + ((size_t)(n*TT+t)*LLEN + 1)*DD + h*64;
        const float* tkp = tek + (size_t)t*DD + h*64;
        const float* tvp = tev + (size_t)t*DD + h*64;
        for (int idx = tid; idx < QQ*16; idx += 256) {
            int k = idx >> 4, c4 = (idx & 15) * 4;
            float4 kv = *(const float4*)(kb + (size_t)k*DD + c4);
            float4 tk = *(const float4*)(tkp + c4);
            int o = k*65 + c4;
            Ks[o]   = kv.x + tk.x; Ks[o+1] = kv.y + tk.y;
            Ks[o+2] = kv.z + tk.z; Ks[o+3] = kv.w + tk.w;
            float4 vv = *(const float4*)(vb + (size_t)k*DD + c4);
            float4 tv = *(const float4*)(tvp + c4);
            float4 r = make_float4(vv.x+tv.x, vv.y+tv.y, vv.z+tv.z, vv.w+tv.w);
            *(float4*)&Vs[k*64 + c4] = r;
        }
        __syncthreads();

        float cA = (sa - ((t==TT-1)?w0a:0.f) - ((t==0)?w2a:0.f)) * (1.f/TT);
        float cB = (sb - ((t==TT-1)?w0b:0.f) - ((t==0)?w2b:0.f)) * (1.f/TT);

        for (int qg = 0; qg < 8; qg++) {
            int q0 = warp*32 + qg*4;
            float aff[4][8];
            #pragma unroll
            for (int qq = 0; qq < 4; qq++)
                #pragma unroll
                for (int ki = 0; ki < 8; ki++) aff[qq][ki] = 0.f;

            const float* r0 = sq_s + (size_t)(q0+0)*64;
            const float* r1 = sq_s + (size_t)(q0+1)*64;
            const float* r2 = sq_s + (size_t)(q0+2)*64;
            const float* r3 = sq_s + (size_t)(q0+3)*64;
            #pragma unroll 4
            for (int c = 0; c < 64; c++) {
                float s0=r0[c], s1=r1[c], s2=r2[c], s3=r3[c];
                #pragma unroll
                for (int ki = 0; ki < 8; ki++) {
                    float kvv = Ks[(ki*32+lane)*65 + c];
                    aff[0][ki] += s0*kvv;
                    aff[1][ki] += s1*kvv;
                    aff[2][ki] += s2*kvv;
                    aff[3][ki] += s3*kvv;
                }
            }

            float* affw = affs + warp*4*256;
            #pragma unroll
            for (int qq = 0; qq < 4; qq++) {
                const float* pmr = pm + (size_t)(q0+qq)*(LLEN-1);
                float mx = -1e30f;
                #pragma unroll
                for (int ki = 0; ki < 8; ki++) {
                    aff[qq][ki] += pmr[ki*32 + lane];
                    mx = fmaxf(mx, aff[qq][ki]);
                }
                #pragma unroll
                for (int o = 16; o; o >>= 1) mx = fmaxf(mx, __shfl_xor_sync(0xffffffffu, mx, o));
                float sum = 0.f;
                #pragma unroll
                for (int ki = 0; ki < 8; ki++) {
                    float e = __expf(aff[qq][ki] - mx);
                    aff[qq][ki] = e; sum += e;
                }
                #pragma unroll
                for (int o = 16; o; o >>= 1) sum += __shfl_xor_sync(0xffffffffu, sum, o);
                float inv = 1.f / sum;
                #pragma unroll
                for (int ki = 0; ki < 8; ki++)
                    affw[qq*256 + ki*32 + lane] = aff[qq][ki] * inv;
            }
            __syncwarp();

            float o0x=0,o0y=0,o1x=0,o1y=0,o2x=0,o2y=0,o3x=0,o3y=0;
            #pragma unroll 4
            for (int k = 0; k < 256; k++) {
                float2 vv = *(const float2*)&Vs[k*64 + c0];
                float a0 = affw[k], a1 = affw[256+k], a2 = affw[512+k], a3 = affw[768+k];
                o0x += a0*vv.x; o0y += a0*vv.y;
                o1x += a1*vv.x; o1y += a1*vv.y;
                o2x += a2*vv.x; o2y += a2*vv.y;
                o3x += a3*vv.x; o3y += a3*vv.y;
            }
            acc[qg*4+0][0] += cA*o0x; acc[qg*4+0][1] += cB*o0y;
            acc[qg*4+1][0] += cA*o1x; acc[qg*4+1][1] += cB*o1y;
            acc[qg*4+2][0] += cA*o2x; acc[qg*4+2][1] += cB*o2y;
            acc[qg*4+3][0] += cA*o3x; acc[qg*4+3][1] += cB*o3y;
            __syncwarp();
        }
    }

    float tbA = tb[d0], tbB = tb[d0+1];
    #pragma unroll
    for (int qi = 0; qi < 32; qi++) {
        int qrow = warp*32 + qi;
        float2 r = make_float2(acc[qi][0] + tbA, acc[qi][1] + tbB);
        *(float2*)&outp[(size_t)(n*QQ+qrow)*DD + d0] = r;
    }
}

// ---------------- launch ----------------
extern "C" void kernel_launch(void* const* d_in, const int* in_sizes, int n_in,
                              void* d_out, int out_size)
{
    const float* attrs_k = (const float*)d_in[0];
    const float* attrs_v = (const float*)d_in[1];
    const float* s       = (const float*)d_in[2];
    const float* te      = (const float*)d_in[3];
    const float* pm      = (const float*)d_in[4];
    const float* ln1w    = (const float*)d_in[5];
    const float* ln1b    = (const float*)d_in[6];
    const float* ipw     = (const float*)d_in[7];
    const float* ipb     = (const float*)d_in[8];
    const float* opw     = (const float*)d_in[9];
    const float* opb     = (const float*)d_in[10];
    const float* ln2w    = (const float*)d_in[11];
    const float* ln2b    = (const float*)d_in[12];
    const float* fcw     = (const float*)d_in[13];
    const float* fcb     = (const float*)d_in[14];
    const float* pjw     = (const float*)d_in[15];
    const float* pjb     = (const float*)d_in[16];
    const float* slnw    = (const float*)d_in[17];
    const float* slnb    = (const float*)d_in[18];
    const float* sl1     = (const float*)d_in[19];
    const float* sl2     = (const float*)d_in[20];
    const float* tlnw    = (const float*)d_in[21];
    const float* tlnb    = (const float*)d_in[22];
    const float* tl1     = (const float*)d_in[23];
    const float* tl2     = (const float*)d_in[24];
    const float* tw      = (const float*)d_in[25];
    const float* tb      = (const float*)d_in[26];
    float* out = (float*)d_out;

    float *ln_buf, *h1, *sadj, *x, *sqb, *mix, *s1, *hmid, *tek, *tev;
    cudaGetSymbolAddress((void**)&ln_buf, g_ln);
    cudaGetSymbolAddress((void**)&h1,     g_h1);
    cudaGetSymbolAddress((void**)&sadj,   g_sadj);
    cudaGetSymbolAddress((void**)&x,      g_x);
    cudaGetSymbolAddress((void**)&sqb,    g_sq);
    cudaGetSymbolAddress((void**)&mix,    g_mix);
    cudaGetSymbolAddress((void**)&s1,     g_s1);
    cudaGetSymbolAddress((void**)&hmid,   g_hmid);
    cudaGetSymbolAddress((void**)&tek,    g_tek);
    cudaGetSymbolAddress((void**)&tev,    g_tev);

    cudaFuncSetAttribute(att_kernel, cudaFuncAttributeMaxDynamicSharedMemorySize, 230400);

    // te path (independent, tiny)
    te_kernel<<<TT, 256>>>(te, tlnw, tlnb, tl1, tl2, ipw, ipb, tek, tev);

    // s adaptor: _s = s + (LN(s) @ l1^T) @ l2^T
    ln_rows_k<<<MROWS, 256>>>(s, slnw, slnb, ln_buf);
    sgemm_nt<0><<<dim3(1, 16), 256>>>(ln_buf, sl1, nullptr, nullptr, h1, MROWS, 128, DD, 1.f);
    sgemm_nt<2><<<dim3(8, 16), 256>>>(h1, sl2, nullptr, s, sadj, MROWS, DD, 128, 1.f);

    // x = LN1(_s); sq = (x @ Wq^T + bq) * (1/sqrt(C))
    ln_rows_k<<<MROWS, 256>>>(sadj, ln1w, ln1b, x);
    sgemm_nt<1><<<dim3(8, 16), 256>>>(x, ipw, ipb, nullptr, sqb, MROWS, DD, DD, 0.125f);

    // fused attention + conv-over-t + mean-over-t
    att_kernel<<<dim3(HH, NB), 256, 230400>>>(sqb, attrs_k, attrs_v, tek, tev, pm, tw, tb, mix);

    // s1 = s + mix @ out_proj^T + b
    sgemm_nt<2><<<dim3(8, 16), 256>>>(mix, opw, opb, s, s1, MROWS, DD, DD, 1.f);

    // MLP
    ln_rows_k<<<MROWS, 256>>>(s1, ln2w, ln2b, x);
    sgemm_nt<3><<<dim3(32, 16), 256>>>(x, fcw, fcb, nullptr, hmid, MROWS, 4*DD, DD, 1.f);
    sgemm_nt<2><<<dim3(8, 16), 256>>>(hmid, pjw, pjb, s1, out, MROWS, DD, 4*DD, 1.f);
}

// round 4
// speedup vs baseline: 1.4286x; 1.4286x over previous
#include <cuda_runtime.h>
#include <math.h>

// Problem dims (fixed)
#define NB 8
#define TT 8
#define LLEN 257
#define HH 16
#define CC 64
#define DD 1024
#define QQ 256
#define MROWS (NB*QQ)   // 2048

// ---------------- scratch (static device arrays; no allocation) ----------------
__device__ float g_ln  [MROWS*DD];
__device__ float g_h1  [MROWS*(DD/8)];
__device__ float g_sadj[MROWS*DD];
__device__ float g_x   [MROWS*DD];
__device__ float g_sq  [MROWS*DD];
__device__ float g_mix [MROWS*DD];
__device__ float g_s1  [MROWS*DD];
__device__ float g_hmid[MROWS*4*DD];
__device__ float g_tek [TT*DD];
__device__ float g_tev [TT*DD];

// ---------------- row LayerNorm ----------------
__global__ __launch_bounds__(256)
void ln_rows_k(const float* __restrict__ in, const float* __restrict__ w,
               const float* __restrict__ b, float* __restrict__ out)
{
    __shared__ float red[18];
    int r = blockIdx.x;
    int tid = threadIdx.x;
    int lane = tid & 31, warp = tid >> 5;
    float4 v = reinterpret_cast<const float4*>(in + (size_t)r*DD)[tid];
    float s = v.x + v.y + v.z + v.w;
    float q = v.x*v.x + v.y*v.y + v.z*v.z + v.w*v.w;
    #pragma unroll
    for (int o = 16; o; o >>= 1) {
        s += __shfl_xor_sync(0xffffffffu, s, o);
        q += __shfl_xor_sync(0xffffffffu, q, o);
    }
    if (lane == 0) { red[warp] = s; red[8+warp] = q; }
    __syncthreads();
    if (tid == 0) {
        float ss = 0.f, qs = 0.f;
        #pragma unroll
        for (int i = 0; i < 8; i++) { ss += red[i]; qs += red[8+i]; }
        red[16] = ss * (1.f/DD);
        red[17] = qs * (1.f/DD);
    }
    __syncthreads();
    float mean = red[16];
    float var  = red[17] - mean*mean;
    float rs   = rsqrtf(var + 1e-5f);
    float4 wv = reinterpret_cast<const float4*>(w)[tid];
    float4 bv = reinterpret_cast<const float4*>(b)[tid];
    float4 o4;
    o4.x = (v.x-mean)*rs*wv.x + bv.x;
    o4.y = (v.y-mean)*rs*wv.y + bv.y;
    o4.z = (v.z-mean)*rs*wv.z + bv.z;
    o4.w = (v.w-mean)*rs*wv.w + bv.w;
    reinterpret_cast<float4*>(out + (size_t)r*DD)[tid] = o4;
}

// ---------------- tf32 helpers ----------------
__device__ __forceinline__ unsigned f2tf(float x) {
    unsigned r;
    asm("cvt.rna.tf32.f32 %0, %1;" : "=r"(r) : "f"(x));
    return r;
}

__device__ __forceinline__ void mma_tf32(float* c, const unsigned* a, const unsigned* b) {
    asm volatile(
        "mma.sync.aligned.m16n8k8.row.col.f32.tf32.tf32.f32 "
        "{%0,%1,%2,%3},{%4,%5,%6,%7},{%8,%9},{%0,%1,%2,%3};"
        : "+f"(c[0]), "+f"(c[1]), "+f"(c[2]), "+f"(c[3])
        : "r"(a[0]), "r"(a[1]), "r"(a[2]), "r"(a[3]), "r"(b[0]), "r"(b[1]));
}

// ---------------- tf32 tensor-core GEMM: C(M,N) = A(M,K) @ W(N,K)^T ----------------
// EPI: 0 = bias only, 1 = (x+bias)*scale, 2 = x+bias+res, 3 = quick_gelu(x+bias)
// Block tile 128x128x16, 8 warps (2 m x 4 n), warp tile 64x32, mma m16n8k8.
// Smem: [row][k] pitch 20 -> fragment LDS bank pattern (r*20+c)%32 is a
// permutation of 0..31 => conflict-free.
template<int EPI>
__global__ __launch_bounds__(256, 2)
void tgemm(const float* __restrict__ A, const float* __restrict__ W,
           const float* __restrict__ bias, const float* __restrict__ res,
           float* __restrict__ C, int M, int N, int K, float scale)
{
    __shared__ unsigned As[2][128][20];
    __shared__ unsigned Bs[2][128][20];

    int tid = threadIdx.x;
    int m0 = blockIdx.y * 128, n0 = blockIdx.x * 128;
    int warp = tid >> 5, lane = tid & 31;
    int wm = warp & 1, wn = warp >> 1;   // 2 x 4 warp grid
    int lr = lane >> 2;                  // 0..7
    int lc = lane & 3;                   // 0..3

    int row = tid >> 2;                  // 0..63
    int k4  = (tid & 3) * 4;

    const float* Ap0 = A + (size_t)(m0+row)*K + k4;
    const float* Ap1 = A + (size_t)(m0+row+64)*K + k4;
    const float* Wp0 = W + (size_t)(n0+row)*K + k4;
    const float* Wp1 = W + (size_t)(n0+row+64)*K + k4;

    float4 pa0 = *(const float4*)Ap0;
    float4 pa1 = *(const float4*)Ap1;
    float4 pw0 = *(const float4*)Wp0;
    float4 pw1 = *(const float4*)Wp1;

    float acc[4][4][4];
    #pragma unroll
    for (int mi = 0; mi < 4; mi++)
        #pragma unroll
        for (int ni = 0; ni < 4; ni++)
            #pragma unroll
            for (int f = 0; f < 4; f++) acc[mi][ni][f] = 0.f;

    // store buffer 0
    {
        uint4 ua0 = make_uint4(f2tf(pa0.x), f2tf(pa0.y), f2tf(pa0.z), f2tf(pa0.w));
        uint4 ua1 = make_uint4(f2tf(pa1.x), f2tf(pa1.y), f2tf(pa1.z), f2tf(pa1.w));
        uint4 uw0 = make_uint4(f2tf(pw0.x), f2tf(pw0.y), f2tf(pw0.z), f2tf(pw0.w));
        uint4 uw1 = make_uint4(f2tf(pw1.x), f2tf(pw1.y), f2tf(pw1.z), f2tf(pw1.w));
        *(uint4*)&As[0][row][k4]    = ua0;
        *(uint4*)&As[0][row+64][k4] = ua1;
        *(uint4*)&Bs[0][row][k4]    = uw0;
        *(uint4*)&Bs[0][row+64][k4] = uw1;
    }
    __syncthreads();

    int nT = K / 16;
    int buf = 0;
    for (int t = 0; t < nT; t++) {
        if (t + 1 < nT) {
            int off = (t+1)*16;
            pa0 = *(const float4*)(Ap0 + off);
            pa1 = *(const float4*)(Ap1 + off);
            pw0 = *(const float4*)(Wp0 + off);
            pw1 = *(const float4*)(Wp1 + off);
        }
        #pragma unroll
        for (int ks = 0; ks < 2; ks++) {
            int kb = ks * 8;
            unsigned af[4][4], bf[4][2];
            #pragma unroll
            for (int mi = 0; mi < 4; mi++) {
                int r = wm*64 + mi*16 + lr;
                int c = kb + lc;
                af[mi][0] = As[buf][r  ][c];
                af[mi][1] = As[buf][r+8][c];
                af[mi][2] = As[buf][r  ][c+4];
                af[mi][3] = As[buf][r+8][c+4];
            }
            #pragma unroll
            for (int ni = 0; ni < 4; ni++) {
                int nn = wn*32 + ni*8 + lr;
                int c = kb + lc;
                bf[ni][0] = Bs[buf][nn][c];
                bf[ni][1] = Bs[buf][nn][c+4];
            }
            #pragma unroll
            for (int mi = 0; mi < 4; mi++)
                #pragma unroll
                for (int ni = 0; ni < 4; ni++)
                    mma_tf32(acc[mi][ni], af[mi], bf[ni]);
        }
        if (t + 1 < nT) {
            buf ^= 1;
            uint4 ua0 = make_uint4(f2tf(pa0.x), f2tf(pa0.y), f2tf(pa0.z), f2tf(pa0.w));
            uint4 ua1 = make_uint4(f2tf(pa1.x), f2tf(pa1.y), f2tf(pa1.z), f2tf(pa1.w));
            uint4 uw0 = make_uint4(f2tf(pw0.x), f2tf(pw0.y), f2tf(pw0.z), f2tf(pw0.w));
            uint4 uw1 = make_uint4(f2tf(pw1.x), f2tf(pw1.y), f2tf(pw1.z), f2tf(pw1.w));
            *(uint4*)&As[buf][row][k4]    = ua0;
            *(uint4*)&As[buf][row+64][k4] = ua1;
            *(uint4*)&Bs[buf][row][k4]    = uw0;
            *(uint4*)&Bs[buf][row+64][k4] = uw1;
            __syncthreads();
        }
    }

    // epilogue
    #pragma unroll
    for (int mi = 0; mi < 4; mi++) {
        int r0 = m0 + wm*64 + mi*16 + lr;
        #pragma unroll
        for (int ni = 0; ni < 4; ni++) {
            int cb = n0 + wn*32 + ni*8 + lc*2;
            float bv0 = 0.f, bv1 = 0.f;
            if (bias) { bv0 = bias[cb]; bv1 = bias[cb+1]; }
            #pragma unroll
            for (int half = 0; half < 2; half++) {
                int r = r0 + half*8;
                float v0 = acc[mi][ni][half*2+0] + bv0;
                float v1 = acc[mi][ni][half*2+1] + bv1;
                if (EPI == 1) { v0 *= scale; v1 *= scale; }
                else if (EPI == 2) {
                    const float* Rr = res + (size_t)r*N + cb;
                    v0 += Rr[0]; v1 += Rr[1];
                }
                else if (EPI == 3) {
                    v0 = v0 / (1.f + __expf(-1.702f * v0));
                    v1 = v1 / (1.f + __expf(-1.702f * v1));
                }
                *(float2*)(C + (size_t)r*N + cb) = make_float2(v0, v1);
            }
        }
    }
}

// ---------------- te path (tiny) ----------------
__global__ __launch_bounds__(256)
void te_kernel(const float* __restrict__ te,
               const float* __restrict__ lnw, const float* __restrict__ lnb,
               const float* __restrict__ l1,  const float* __restrict__ l2,
               const float* __restrict__ ipw, const float* __restrict__ ipb,
               float* __restrict__ tek, float* __restrict__ tev)
{
    __shared__ float row[DD];
    __shared__ float lnr[DD];
    __shared__ float hb[256];
    __shared__ float hs[128];
    __shared__ float red[18];
    int t = blockIdx.x, tid = threadIdx.x;
    int lane = tid & 31, warp = tid >> 5;

    float4 v = reinterpret_cast<const float4*>(te + (size_t)t*DD)[tid];
    reinterpret_cast<float4*>(row)[tid] = v;
    float s = v.x+v.y+v.z+v.w;
    float q = v.x*v.x+v.y*v.y+v.z*v.z+v.w*v.w;
    #pragma unroll
    for (int o = 16; o; o >>= 1) {
        s += __shfl_xor_sync(0xffffffffu, s, o);
        q += __shfl_xor_sync(0xffffffffu, q, o);
    }
    if (lane == 0) { red[warp] = s; red[8+warp] = q; }
    __syncthreads();
    if (tid == 0) {
        float ss=0.f, qs=0.f;
        #pragma unroll
        for (int i=0;i<8;i++){ ss+=red[i]; qs+=red[8+i]; }
        red[16]=ss*(1.f/DD); red[17]=qs*(1.f/DD);
    }
    __syncthreads();
    float mean = red[16];
    float rs   = rsqrtf(red[17] - mean*mean + 1e-5f);
    float4 wv = reinterpret_cast<const float4*>(lnw)[tid];
    float4 bv = reinterpret_cast<const float4*>(lnb)[tid];
    float4 o4;
    o4.x=(v.x-mean)*rs*wv.x+bv.x; o4.y=(v.y-mean)*rs*wv.y+bv.y;
    o4.z=(v.z-mean)*rs*wv.z+bv.z; o4.w=(v.w-mean)*rs*wv.w+bv.w;
    reinterpret_cast<float4*>(lnr)[tid] = o4;
    __syncthreads();

    {
        int j = tid & 127, half = tid >> 7;
        const float4* wr = (const float4*)(l1 + (size_t)j*DD + half*512);
        const float4* xr = (const float4*)(lnr + half*512);
        float p = 0.f;
        #pragma unroll 8
        for (int k = 0; k < 128; k++) {
            float4 w4 = wr[k]; float4 x4 = xr[k];
            p += w4.x*x4.x + w4.y*x4.y + w4.z*x4.z + w4.w*x4.w;
        }
        hb[tid] = p;
    }
    __syncthreads();
    if (tid < 128) hs[tid] = hb[tid] + hb[tid+128];
    __syncthreads();

    float outv[4];
    #pragma unroll
    for (int ii = 0; ii < 4; ii++) {
        int i = tid + ii*256;
        const float* w2r = l2 + (size_t)i*128;
        float p = 0.f;
        #pragma unroll 8
        for (int j = 0; j < 128; j++) p += hs[j]*w2r[j];
        outv[ii] = row[i] + p;
    }
    __syncthreads();
    #pragma unroll
    for (int ii = 0; ii < 4; ii++) lnr[tid + ii*256] = outv[ii];
    __syncthreads();

    for (int o = tid; o < 2*DD; o += 256) {
        const float4* wr = (const float4*)(ipw + (size_t)(DD+o)*DD);
        float p = ipb[DD + o];
        #pragma unroll 8
        for (int d4 = 0; d4 < 256; d4++) {
            float4 w4 = wr[d4];
            float4 x4 = ((float4*)lnr)[d4];
            p += w4.x*x4.x + w4.y*x4.y + w4.z*x4.z + w4.w*x4.w;
        }
        if (o < DD) tek[(size_t)t*DD + o] = p;
        else        tev[(size_t)t*DD + (o-DD)] = p;
    }
}

// ---------------- attention + depthwise conv-over-t + mean-over-t (fused) ----------------
__global__ __launch_bounds__(256, 1)
void att_kernel(const float* __restrict__ sq, const float* __restrict__ ak,
                const float* __restrict__ av, const float* __restrict__ tek,
                const float* __restrict__ tev, const float* __restrict__ pm,
                const float* __restrict__ tw, const float* __restrict__ tb,
                float* __restrict__ outp)
{
    extern __shared__ float sm[];
    float* sq_s = sm;               // 256*64
    float* Ks   = sm + 16384;       // 256*65
    float* Vs   = Ks + 16640;       // 256*64
    float* affs = Vs + 16384;       // 8 warps * 4 q * 256 k

    int h = blockIdx.x, n = blockIdx.y;
    int tid = threadIdx.x, warp = tid >> 5, lane = tid & 31;

    for (int idx = tid; idx < QQ*16; idx += 256) {
        int qr = idx >> 4, c4 = (idx & 15) * 4;
        *(float4*)&sq_s[qr*64 + c4] =
            *(const float4*)(sq + (size_t)(n*QQ+qr)*DD + h*64 + c4);
    }

    int c0 = lane*2;
    int d0 = h*64 + c0;
    float w0a = tw[d0*3+0],     w1a = tw[d0*3+1],     w2a = tw[d0*3+2];
    float w0b = tw[(d0+1)*3+0], w1b = tw[(d0+1)*3+1], w2b = tw[(d0+1)*3+2];
    float sa = 1.f + w0a + w1a + w2a;
    float sb = 1.f + w0b + w1b + w2b;

    float acc[32][2];
    #pragma unroll
    for (int i = 0; i < 32; i++) { acc[i][0] = 0.f; acc[i][1] = 0.f; }

    for (int t = 0; t < TT; t++) {
        __syncthreads();
        const float* kb  = ak  + ((size_t)(n*TT+t)*LLEN + 1)*DD + h*64;
        const float* vb  = av  + ((size_t)(n*TT+t)*LLEN + 1)*DD + h*64;
        const float* tkp = tek + (size_t)t*DD + h*64;
        const float* tvp = tev + (size_t)t*DD + h*64;
        for (int idx = tid; idx < QQ*16; idx += 256) {
            int k = idx >> 4, c4 = (idx & 15) * 4;
            float4 kv = *(const float4*)(kb + (size_t)k*DD + c4);
            float4 tk = *(const float4*)(tkp + c4);
            int o = k*65 + c4;
            Ks[o]   = kv.x + tk.x; Ks[o+1] = kv.y + tk.y;
            Ks[o+2] = kv.z + tk.z; Ks[o+3] = kv.w + tk.w;
            float4 vv = *(const float4*)(vb + (size_t)k*DD + c4);
            float4 tv = *(const float4*)(tvp + c4);
            float4 r = make_float4(vv.x+tv.x, vv.y+tv.y, vv.z+tv.z, vv.w+tv.w);
            *(float4*)&Vs[k*64 + c4] = r;
        }
        __syncthreads();

        float cA = (sa - ((t==TT-1)?w0a:0.f) - ((t==0)?w2a:0.f)) * (1.f/TT);
        float cB = (sb - ((t==TT-1)?w0b:0.f) - ((t==0)?w2b:0.f)) * (1.f/TT);

        for (int qg = 0; qg < 8; qg++) {
            int q0 = warp*32 + qg*4;
            float aff[4][8];
            #pragma unroll
            for (int qq = 0; qq < 4; qq++)
                #pragma unroll
                for (int ki = 0; ki < 8; ki++) aff[qq][ki] = 0.f;

            const float* r0 = sq_s + (size_t)(q0+0)*64;
            const float* r1 = sq_s + (size_t)(q0+1)*64;
            const float* r2 = sq_s + (size_t)(q0+2)*64;
            const float* r3 = sq_s + (size_t)(q0+3)*64;
            #pragma unroll 4
            for (int c = 0; c < 64; c++) {
                float s0=r0[c], s1=r1[c], s2=r2[c], s3=r3[c];
                #pragma unroll
                for (int ki = 0; ki < 8; ki++) {
                    float kvv = Ks[(ki*32+lane)*65 + c];
                    aff[0][ki] += s0*kvv;
                    aff[1][ki] += s1*kvv;
                    aff[2][ki] += s2*kvv;
                    aff[3][ki] += s3*kvv;
                }
            }

            float* affw = affs + warp*4*256;
            #pragma unroll
            for (int qq = 0; qq < 4; qq++) {
                const float* pmr = pm + (size_t)(q0+qq)*(LLEN-1);
                float mx = -1e30f;
                #pragma unroll
                for (int ki = 0; ki < 8; ki++) {
                    aff[qq][ki] += pmr[ki*32 + lane];
                    mx = fmaxf(mx, aff[qq][ki]);
                }
                #pragma unroll
                for (int o = 16; o; o >>= 1) mx = fmaxf(mx, __shfl_xor_sync(0xffffffffu, mx, o));
                float sum = 0.f;
                #pragma unroll
                for (int ki = 0; ki < 8; ki++) {
                    float e = __expf(aff[qq][ki] - mx);
                    aff[qq][ki] = e; sum += e;
                }
                #pragma unroll
                for (int o = 16; o; o >>= 1) sum += __shfl_xor_sync(0xffffffffu, sum, o);
                float inv = 1.f / sum;
                #pragma unroll
                for (int ki = 0; ki < 8; ki++)
                    affw[qq*256 + ki*32 + lane] = aff[qq][ki] * inv;
            }
            __syncwarp();

            float o0x=0,o0y=0,o1x=0,o1y=0,o2x=0,o2y=0,o3x=0,o3y=0;
            #pragma unroll 4
            for (int k = 0; k < 256; k++) {
                float2 vv = *(const float2*)&Vs[k*64 + c0];
                float a0 = affw[k], a1 = affw[256+k], a2 = affw[512+k], a3 = affw[768+k];
                o0x += a0*vv.x; o0y += a0*vv.y;
                o1x += a1*vv.x; o1y += a1*vv.y;
                o2x += a2*vv.x; o2y += a2*vv.y;
                o3x += a3*vv.x; o3y += a3*vv.y;
            }
            acc[qg*4+0][0] += cA*o0x; acc[qg*4+0][1] += cB*o0y;
            acc[qg*4+1][0] += cA*o1x; acc[qg*4+1][1] += cB*o1y;
            acc[qg*4+2][0] += cA*o2x; acc[qg*4+2][1] += cB*o2y;
            acc[qg*4+3][0] += cA*o3x; acc[qg*4+3][1] += cB*o3y;
            __syncwarp();
        }
    }

    float tbA = tb[d0], tbB = tb[d0+1];
    #pragma unroll
    for (int qi = 0; qi < 32; qi++) {
        int qrow = warp*32 + qi;
        float2 r = make_float2(acc[qi][0] + tbA, acc[qi][1] + tbB);
        *(float2*)&outp[(size_t)(n*QQ+qrow)*DD + d0] = r;
    }
}

// ---------------- launch ----------------
extern "C" void kernel_launch(void* const* d_in, const int* in_sizes, int n_in,
                              void* d_out, int out_size)
{
    const float* attrs_k = (const float*)d_in[0];
    const float* attrs_v = (const float*)d_in[1];
    const float* s       = (const float*)d_in[2];
    const float* te      = (const float*)d_in[3];
    const float* pm      = (const float*)d_in[4];
    const float* ln1w    = (const float*)d_in[5];
    const float* ln1b    = (const float*)d_in[6];
    const float* ipw     = (const float*)d_in[7];
    const float* ipb     = (const float*)d_in[8];
    const float* opw     = (const float*)d_in[9];
    const float* opb     = (const float*)d_in[10];
    const float* ln2w    = (const float*)d_in[11];
    const float* ln2b    = (const float*)d_in[12];
    const float* fcw     = (const float*)d_in[13];
    const float* fcb     = (const float*)d_in[14];
    const float* pjw     = (const float*)d_in[15];
    const float* pjb     = (const float*)d_in[16];
    const float* slnw    = (const float*)d_in[17];
    const float* slnb    = (const float*)d_in[18];
    const float* sl1     = (const float*)d_in[19];
    const float* sl2     = (const float*)d_in[20];
    const float* tlnw    = (const float*)d_in[21];
    const float* tlnb    = (const float*)d_in[22];
    const float* tl1     = (const float*)d_in[23];
    const float* tl2     = (const float*)d_in[24];
    const float* tw      = (const float*)d_in[25];
    const float* tb      = (const float*)d_in[26];
    float* out = (float*)d_out;

    float *ln_buf, *h1, *sadj, *x, *sqb, *mix, *s1, *hmid, *tek, *tev;
    cudaGetSymbolAddress((void**)&ln_buf, g_ln);
    cudaGetSymbolAddress((void**)&h1,     g_h1);
    cudaGetSymbolAddress((void**)&sadj,   g_sadj);
    cudaGetSymbolAddress((void**)&x,      g_x);
    cudaGetSymbolAddress((void**)&sqb,    g_sq);
    cudaGetSymbolAddress((void**)&mix,    g_mix);
    cudaGetSymbolAddress((void**)&s1,     g_s1);
    cudaGetSymbolAddress((void**)&hmid,   g_hmid);
    cudaGetSymbolAddress((void**)&tek,    g_tek);
    cudaGetSymbolAddress((void**)&tev,    g_tev);

    cudaFuncSetAttribute(att_kernel, cudaFuncAttributeMaxDynamicSharedMemorySize, 230400);

    // te path (independent, tiny)
    te_kernel<<<TT, 256>>>(te, tlnw, tlnb, tl1, tl2, ipw, ipb, tek, tev);

    // s adaptor: _s = s + (LN(s) @ l1^T) @ l2^T
    ln_rows_k<<<MROWS, 256>>>(s, slnw, slnb, ln_buf);
    tgemm<0><<<dim3(1, 16), 256>>>(ln_buf, sl1, nullptr, nullptr, h1, MROWS, 128, DD, 1.f);
    tgemm<2><<<dim3(8, 16), 256>>>(h1, sl2, nullptr, s, sadj, MROWS, DD, 128, 1.f);

    // x = LN1(_s); sq = (x @ Wq^T + bq) * (1/sqrt(C))
    ln_rows_k<<<MROWS, 256>>>(sadj, ln1w, ln1b, x);
    tgemm<1><<<dim3(8, 16), 256>>>(x, ipw, ipb, nullptr, sqb, MROWS, DD, DD, 0.125f);

    // fused attention + conv-over-t + mean-over-t
    att_kernel<<<dim3(HH, NB), 256, 230400>>>(sqb, attrs_k, attrs_v, tek, tev, pm, tw, tb, mix);

    // s1 = s + mix @ out_proj^T + b
    tgemm<2><<<dim3(8, 16), 256>>>(mix, opw, opb, s, s1, MROWS, DD, DD, 1.f);

    // MLP
    ln_rows_k<<<MROWS, 256>>>(s1, ln2w, ln2b, x);
    tgemm<3><<<dim3(32, 16), 256>>>(x, fcw, fcb, nullptr, hmid, MROWS, 4*DD, DD, 1.f);
    tgemm<2><<<dim3(8, 16), 256>>>(hmid, pjw, pjb, s1, out, MROWS, DD, 4*DD, 1.f);
}

// round 5
// speedup vs baseline: 2.0812x; 1.4568x over previous
#include <cuda_runtime.h>
#include <math.h>

// Problem dims (fixed)
#define NB 8
#define TT 8
#define LLEN 257
#define HH 16
#define CC 64
#define DD 1024
#define QQ 256
#define MROWS (NB*QQ)   // 2048

// ---------------- scratch (static device arrays; no allocation) ----------------
__device__ float g_ln  [MROWS*DD];
__device__ float g_h1  [MROWS*(DD/8)];
__device__ float g_sadj[MROWS*DD];
__device__ float g_x   [MROWS*DD];
__device__ float g_sq  [MROWS*DD];
__device__ float g_mix [MROWS*DD];
__device__ float g_s1  [MROWS*DD];
__device__ float g_hmid[MROWS*4*DD];
__device__ float g_tek [TT*DD];
__device__ float g_tev [TT*DD];

// ---------------- row LayerNorm ----------------
__global__ __launch_bounds__(256)
void ln_rows_k(const float* __restrict__ in, const float* __restrict__ w,
               const float* __restrict__ b, float* __restrict__ out)
{
    __shared__ float red[18];
    int r = blockIdx.x;
    int tid = threadIdx.x;
    int lane = tid & 31, warp = tid >> 5;
    float4 v = reinterpret_cast<const float4*>(in + (size_t)r*DD)[tid];
    float s = v.x + v.y + v.z + v.w;
    float q = v.x*v.x + v.y*v.y + v.z*v.z + v.w*v.w;
    #pragma unroll
    for (int o = 16; o; o >>= 1) {
        s += __shfl_xor_sync(0xffffffffu, s, o);
        q += __shfl_xor_sync(0xffffffffu, q, o);
    }
    if (lane == 0) { red[warp] = s; red[8+warp] = q; }
    __syncthreads();
    if (tid == 0) {
        float ss = 0.f, qs = 0.f;
        #pragma unroll
        for (int i = 0; i < 8; i++) { ss += red[i]; qs += red[8+i]; }
        red[16] = ss * (1.f/DD);
        red[17] = qs * (1.f/DD);
    }
    __syncthreads();
    float mean = red[16];
    float var  = red[17] - mean*mean;
    float rs   = rsqrtf(var + 1e-5f);
    float4 wv = reinterpret_cast<const float4*>(w)[tid];
    float4 bv = reinterpret_cast<const float4*>(b)[tid];
    float4 o4;
    o4.x = (v.x-mean)*rs*wv.x + bv.x;
    o4.y = (v.y-mean)*rs*wv.y + bv.y;
    o4.z = (v.z-mean)*rs*wv.z + bv.z;
    o4.w = (v.w-mean)*rs*wv.w + bv.w;
    reinterpret_cast<float4*>(out + (size_t)r*DD)[tid] = o4;
}

// ---------------- tf32 helpers ----------------
__device__ __forceinline__ unsigned f2tf(float x) {
    unsigned r;
    asm("cvt.rna.tf32.f32 %0, %1;" : "=r"(r) : "f"(x));
    return r;
}

__device__ __forceinline__ void mma_tf32(float* c, const unsigned* a, const unsigned* b) {
    asm volatile(
        "mma.sync.aligned.m16n8k8.row.col.f32.tf32.tf32.f32 "
        "{%0,%1,%2,%3},{%4,%5,%6,%7},{%8,%9},{%0,%1,%2,%3};"
        : "+f"(c[0]), "+f"(c[1]), "+f"(c[2]), "+f"(c[3])
        : "r"(a[0]), "r"(a[1]), "r"(a[2]), "r"(a[3]), "r"(b[0]), "r"(b[1]));
}

// ---------------- tf32 tensor-core GEMM: C(M,N) = A(M,K) @ W(N,K)^T ----------------
template<int EPI>
__global__ __launch_bounds__(256, 2)
void tgemm(const float* __restrict__ A, const float* __restrict__ W,
           const float* __restrict__ bias, const float* __restrict__ res,
           float* __restrict__ C, int M, int N, int K, float scale)
{
    __shared__ unsigned As[2][128][20];
    __shared__ unsigned Bs[2][128][20];

    int tid = threadIdx.x;
    int m0 = blockIdx.y * 128, n0 = blockIdx.x * 128;
    int warp = tid >> 5, lane = tid & 31;
    int wm = warp & 1, wn = warp >> 1;
    int lr = lane >> 2;
    int lc = lane & 3;

    int row = tid >> 2;
    int k4  = (tid & 3) * 4;

    const float* Ap0 = A + (size_t)(m0+row)*K + k4;
    const float* Ap1 = A + (size_t)(m0+row+64)*K + k4;
    const float* Wp0 = W + (size_t)(n0+row)*K + k4;
    const float* Wp1 = W + (size_t)(n0+row+64)*K + k4;

    float4 pa0 = *(const float4*)Ap0;
    float4 pa1 = *(const float4*)Ap1;
    float4 pw0 = *(const float4*)Wp0;
    float4 pw1 = *(const float4*)Wp1;

    float acc[4][4][4];
    #pragma unroll
    for (int mi = 0; mi < 4; mi++)
        #pragma unroll
        for (int ni = 0; ni < 4; ni++)
            #pragma unroll
            for (int f = 0; f < 4; f++) acc[mi][ni][f] = 0.f;

    {
        uint4 ua0 = make_uint4(f2tf(pa0.x), f2tf(pa0.y), f2tf(pa0.z), f2tf(pa0.w));
        uint4 ua1 = make_uint4(f2tf(pa1.x), f2tf(pa1.y), f2tf(pa1.z), f2tf(pa1.w));
        uint4 uw0 = make_uint4(f2tf(pw0.x), f2tf(pw0.y), f2tf(pw0.z), f2tf(pw0.w));
        uint4 uw1 = make_uint4(f2tf(pw1.x), f2tf(pw1.y), f2tf(pw1.z), f2tf(pw1.w));
        *(uint4*)&As[0][row][k4]    = ua0;
        *(uint4*)&As[0][row+64][k4] = ua1;
        *(uint4*)&Bs[0][row][k4]    = uw0;
        *(uint4*)&Bs[0][row+64][k4] = uw1;
    }
    __syncthreads();

    int nT = K / 16;
    int buf = 0;
    for (int t = 0; t < nT; t++) {
        if (t + 1 < nT) {
            int off = (t+1)*16;
            pa0 = *(const float4*)(Ap0 + off);
            pa1 = *(const float4*)(Ap1 + off);
            pw0 = *(const float4*)(Wp0 + off);
            pw1 = *(const float4*)(Wp1 + off);
        }
        #pragma unroll
        for (int ks = 0; ks < 2; ks++) {
            int kb = ks * 8;
            unsigned af[4][4], bf[4][2];
            #pragma unroll
            for (int mi = 0; mi < 4; mi++) {
                int r = wm*64 + mi*16 + lr;
                int c = kb + lc;
                af[mi][0] = As[buf][r  ][c];
                af[mi][1] = As[buf][r+8][c];
                af[mi][2] = As[buf][r  ][c+4];
                af[mi][3] = As[buf][r+8][c+4];
            }
            #pragma unroll
            for (int ni = 0; ni < 4; ni++) {
                int nn = wn*32 + ni*8 + lr;
                int c = kb + lc;
                bf[ni][0] = Bs[buf][nn][c];
                bf[ni][1] = Bs[buf][nn][c+4];
            }
            #pragma unroll
            for (int mi = 0; mi < 4; mi++)
                #pragma unroll
                for (int ni = 0; ni < 4; ni++)
                    mma_tf32(acc[mi][ni], af[mi], bf[ni]);
        }
        if (t + 1 < nT) {
            buf ^= 1;
            uint4 ua0 = make_uint4(f2tf(pa0.x), f2tf(pa0.y), f2tf(pa0.z), f2tf(pa0.w));
            uint4 ua1 = make_uint4(f2tf(pa1.x), f2tf(pa1.y), f2tf(pa1.z), f2tf(pa1.w));
            uint4 uw0 = make_uint4(f2tf(pw0.x), f2tf(pw0.y), f2tf(pw0.z), f2tf(pw0.w));
            uint4 uw1 = make_uint4(f2tf(pw1.x), f2tf(pw1.y), f2tf(pw1.z), f2tf(pw1.w));
            *(uint4*)&As[buf][row][k4]    = ua0;
            *(uint4*)&As[buf][row+64][k4] = ua1;
            *(uint4*)&Bs[buf][row][k4]    = uw0;
            *(uint4*)&Bs[buf][row+64][k4] = uw1;
            __syncthreads();
        }
    }

    #pragma unroll
    for (int mi = 0; mi < 4; mi++) {
        int r0 = m0 + wm*64 + mi*16 + lr;
        #pragma unroll
        for (int ni = 0; ni < 4; ni++) {
            int cb = n0 + wn*32 + ni*8 + lc*2;
            float bv0 = 0.f, bv1 = 0.f;
            if (bias) { bv0 = bias[cb]; bv1 = bias[cb+1]; }
            #pragma unroll
            for (int half = 0; half < 2; half++) {
                int r = r0 + half*8;
                float v0 = acc[mi][ni][half*2+0] + bv0;
                float v1 = acc[mi][ni][half*2+1] + bv1;
                if (EPI == 1) { v0 *= scale; v1 *= scale; }
                else if (EPI == 2) {
                    const float* Rr = res + (size_t)r*N + cb;
                    v0 += Rr[0]; v1 += Rr[1];
                }
                else if (EPI == 3) {
                    v0 = v0 / (1.f + __expf(-1.702f * v0));
                    v1 = v1 / (1.f + __expf(-1.702f * v1));
                }
                *(float2*)(C + (size_t)r*N + cb) = make_float2(v0, v1);
            }
        }
    }
}

// ---------------- te path (tiny) ----------------
__global__ __launch_bounds__(256)
void te_kernel(const float* __restrict__ te,
               const float* __restrict__ lnw, const float* __restrict__ lnb,
               const float* __restrict__ l1,  const float* __restrict__ l2,
               const float* __restrict__ ipw, const float* __restrict__ ipb,
               float* __restrict__ tek, float* __restrict__ tev)
{
    __shared__ float row[DD];
    __shared__ float lnr[DD];
    __shared__ float hb[256];
    __shared__ float hs[128];
    __shared__ float red[18];
    int t = blockIdx.x, tid = threadIdx.x;
    int lane = tid & 31, warp = tid >> 5;

    float4 v = reinterpret_cast<const float4*>(te + (size_t)t*DD)[tid];
    reinterpret_cast<float4*>(row)[tid] = v;
    float s = v.x+v.y+v.z+v.w;
    float q = v.x*v.x+v.y*v.y+v.z*v.z+v.w*v.w;
    #pragma unroll
    for (int o = 16; o; o >>= 1) {
        s += __shfl_xor_sync(0xffffffffu, s, o);
        q += __shfl_xor_sync(0xffffffffu, q, o);
    }
    if (lane == 0) { red[warp] = s; red[8+warp] = q; }
    __syncthreads();
    if (tid == 0) {
        float ss=0.f, qs=0.f;
        #pragma unroll
        for (int i=0;i<8;i++){ ss+=red[i]; qs+=red[8+i]; }
        red[16]=ss*(1.f/DD); red[17]=qs*(1.f/DD);
    }
    __syncthreads();
    float mean = red[16];
    float rs   = rsqrtf(red[17] - mean*mean + 1e-5f);
    float4 wv = reinterpret_cast<const float4*>(lnw)[tid];
    float4 bv = reinterpret_cast<const float4*>(lnb)[tid];
    float4 o4;
    o4.x=(v.x-mean)*rs*wv.x+bv.x; o4.y=(v.y-mean)*rs*wv.y+bv.y;
    o4.z=(v.z-mean)*rs*wv.z+bv.z; o4.w=(v.w-mean)*rs*wv.w+bv.w;
    reinterpret_cast<float4*>(lnr)[tid] = o4;
    __syncthreads();

    {
        int j = tid & 127, half = tid >> 7;
        const float4* wr = (const float4*)(l1 + (size_t)j*DD + half*512);
        const float4* xr = (const float4*)(lnr + half*512);
        float p = 0.f;
        #pragma unroll 8
        for (int k = 0; k < 128; k++) {
            float4 w4 = wr[k]; float4 x4 = xr[k];
            p += w4.x*x4.x + w4.y*x4.y + w4.z*x4.z + w4.w*x4.w;
        }
        hb[tid] = p;
    }
    __syncthreads();
    if (tid < 128) hs[tid] = hb[tid] + hb[tid+128];
    __syncthreads();

    float outv[4];
    #pragma unroll
    for (int ii = 0; ii < 4; ii++) {
        int i = tid + ii*256;
        const float* w2r = l2 + (size_t)i*128;
        float p = 0.f;
        #pragma unroll 8
        for (int j = 0; j < 128; j++) p += hs[j]*w2r[j];
        outv[ii] = row[i] + p;
    }
    __syncthreads();
    #pragma unroll
    for (int ii = 0; ii < 4; ii++) lnr[tid + ii*256] = outv[ii];
    __syncthreads();

    for (int o = tid; o < 2*DD; o += 256) {
        const float4* wr = (const float4*)(ipw + (size_t)(DD+o)*DD);
        float p = ipb[DD + o];
        #pragma unroll 8
        for (int d4 = 0; d4 < 256; d4++) {
            float4 w4 = wr[d4];
            float4 x4 = ((float4*)lnr)[d4];
            p += w4.x*x4.x + w4.y*x4.y + w4.z*x4.z + w4.w*x4.w;
        }
        if (o < DD) tek[(size_t)t*DD + o] = p;
        else        tev[(size_t)t*DD + (o-DD)] = p;
    }
}

// ---------------- tf32 MMA attention + conv-over-t + mean-over-t (fused) ----------------
// grid (H, N), 256 threads (8 warps). Per CTA: 256 q x (8 t x 256 keys) x 64 c.
// Warp handles 16 q rows per pass, 2 passes. Keys chunked by 64.
// No-max softmax (score magnitudes ~sigma 1; exp overflow impossible).
// Smem (unsigned/float words): sq[256*68] | Ks[256*68] | Vs[256*68] | chan[192]
#define APITCH 68
#define ATT_SMEM_WORDS (3*256*APITCH + 192)

__global__ __launch_bounds__(256, 1)
void att_mma(const float* __restrict__ sq, const float* __restrict__ ak,
             const float* __restrict__ av, const float* __restrict__ tek,
             const float* __restrict__ tev, const float* __restrict__ pm,
             const float* __restrict__ tw, const float* __restrict__ tb,
             float* __restrict__ outp)
{
    extern __shared__ unsigned sm[];
    unsigned* sq_s = sm;                    // [256][68] tf32 Q (pre-scaled)
    unsigned* Ks   = sm + 256*APITCH;       // [256][68] tf32 K+te_k
    unsigned* Vs   = Ks + 256*APITCH;       // [256][68] tf32 V+te_v
    float* chS  = (float*)(Vs + 256*APITCH); // [64] (1+w0+w1+w2)/8
    float* chW0 = chS + 64;                  // [64] w0/8
    float* chW2 = chW0 + 64;                 // [64] w2/8

    int h = blockIdx.x, n = blockIdx.y;
    int tid = threadIdx.x, warp = tid >> 5, lane = tid & 31;
    int lr = lane >> 2, lc = lane & 3;

    // stage Q as tf32
    for (int idx = tid; idx < QQ*16; idx += 256) {
        int q = idx >> 4, c4 = (idx & 15) * 4;
        float4 v = *(const float4*)(sq + (size_t)(n*QQ+q)*DD + h*64 + c4);
        *(uint4*)&sq_s[q*APITCH + c4] =
            make_uint4(f2tf(v.x), f2tf(v.y), f2tf(v.z), f2tf(v.w));
    }
    if (tid < 64) {
        int d = h*64 + tid;
        float w0 = tw[d*3+0], w1 = tw[d*3+1], w2 = tw[d*3+2];
        chS[tid]  = (1.f + w0 + w1 + w2) * 0.125f;
        chW0[tid] = w0 * 0.125f;
        chW2[tid] = w2 * 0.125f;
    }

    float acc[2][32];
    #pragma unroll
    for (int p = 0; p < 2; p++)
        #pragma unroll
        for (int i = 0; i < 32; i++) acc[p][i] = 0.f;

    int quadbase = lane & ~3;

    for (int t = 0; t < TT; t++) {
        __syncthreads();   // prior reads of Ks/Vs done (also covers Q/chan staging at t=0)
        const float* kb  = ak  + ((size_t)(n*TT+t)*LLEN + 1)*DD + h*64;
        const float* vb  = av  + ((size_t)(n*TT+t)*LLEN + 1)*DD + h*64;
        const float* tkp = tek + (size_t)t*DD + h*64;
        const float* tvp = tev + (size_t)t*DD + h*64;
        for (int idx = tid; idx < QQ*16; idx += 256) {
            int k = idx >> 4, c4 = (idx & 15) * 4;
            float4 kv = *(const float4*)(kb + (size_t)k*DD + c4);
            float4 tk = *(const float4*)(tkp + c4);
            *(uint4*)&Ks[k*APITCH + c4] = make_uint4(
                f2tf(kv.x+tk.x), f2tf(kv.y+tk.y), f2tf(kv.z+tk.z), f2tf(kv.w+tk.w));
            float4 vv = *(const float4*)(vb + (size_t)k*DD + c4);
            float4 tv = *(const float4*)(tvp + c4);
            *(uint4*)&Vs[k*APITCH + c4] = make_uint4(
                f2tf(vv.x+tv.x), f2tf(vv.y+tv.y), f2tf(vv.z+tv.z), f2tf(vv.w+tv.w));
        }
        __syncthreads();

        #pragma unroll
        for (int pass = 0; pass < 2; pass++) {
            int qb = pass*128 + warp*16;

            // Q A-fragments (16 q x 64 c -> 8 k-steps)
            unsigned aq[8][4];
            #pragma unroll
            for (int ks = 0; ks < 8; ks++) {
                int c = ks*8 + lc;
                aq[ks][0] = sq_s[(qb+lr  )*APITCH + c];
                aq[ks][1] = sq_s[(qb+lr+8)*APITCH + c];
                aq[ks][2] = sq_s[(qb+lr  )*APITCH + c+4];
                aq[ks][3] = sq_s[(qb+lr+8)*APITCH + c+4];
            }

            float curO[8][4];
            #pragma unroll
            for (int i = 0; i < 8; i++)
                #pragma unroll
                for (int f = 0; f < 4; f++) curO[i][f] = 0.f;
            float l0 = 0.f, l1 = 0.f;

            for (int chunk = 0; chunk < 4; chunk++) {
                int k0 = chunk*64;

                // S = Q @ K^T  (16q x 64k chunk)
                float S[8][4];
                #pragma unroll
                for (int i = 0; i < 8; i++)
                    #pragma unroll
                    for (int f = 0; f < 4; f++) S[i][f] = 0.f;
                #pragma unroll
                for (int ks = 0; ks < 8; ks++) {
                    #pragma unroll
                    for (int nt = 0; nt < 8; nt++) {
                        unsigned bfr[2];
                        bfr[0] = Ks[(k0 + nt*8 + lr)*APITCH + ks*8 + lc];
                        bfr[1] = Ks[(k0 + nt*8 + lr)*APITCH + ks*8 + lc + 4];
                        mma_tf32(S[nt], aq[ks], bfr);
                    }
                }

                // mask + exp + row-sum + build P A-frags (C-frag -> A-frag via quad shfl)
                unsigned aP[8][4];
                #pragma unroll
                for (int nt = 0; nt < 8; nt++) {
                    int kcol = k0 + nt*8 + 2*lc;
                    const float* pmr = pm + (size_t)(qb+lr)*(LLEN-1) + kcol;
                    float2 m0 = *(const float2*)pmr;
                    float2 m1 = *(const float2*)(pmr + 8*(LLEN-1));
                    float p0 = __expf(S[nt][0] + m0.x);
                    float p1 = __expf(S[nt][1] + m0.y);
                    float p2 = __expf(S[nt][2] + m1.x);
                    float p3 = __expf(S[nt][3] + m1.y);
                    l0 += p0 + p1;
                    l1 += p2 + p3;
                    int srcA = quadbase | (lc >> 1);
                    int srcB = srcA + 2;
                    float t0a = __shfl_sync(0xffffffffu, p0, srcA);
                    float t0b = __shfl_sync(0xffffffffu, p1, srcA);
                    float t2a = __shfl_sync(0xffffffffu, p0, srcB);
                    float t2b = __shfl_sync(0xffffffffu, p1, srcB);
                    float t1a = __shfl_sync(0xffffffffu, p2, srcA);
                    float t1b = __shfl_sync(0xffffffffu, p3, srcA);
                    float t3a = __shfl_sync(0xffffffffu, p2, srcB);
                    float t3b = __shfl_sync(0xffffffffu, p3, srcB);
                    bool odd = (lc & 1);
                    aP[nt][0] = f2tf(odd ? t0b : t0a);
                    aP[nt][1] = f2tf(odd ? t1b : t1a);
                    aP[nt][2] = f2tf(odd ? t2b : t2a);
                    aP[nt][3] = f2tf(odd ? t3b : t3a);
                }

                // curO += P @ V  (16q x 64c), keys of this chunk as k-dim
                #pragma unroll
                for (int ks = 0; ks < 8; ks++) {
                    #pragma unroll
                    for (int nc = 0; nc < 8; nc++) {
                        unsigned bfr[2];
                        bfr[0] = Vs[(k0 + ks*8 + lc    )*APITCH + nc*8 + lr];
                        bfr[1] = Vs[(k0 + ks*8 + lc + 4)*APITCH + nc*8 + lr];
                        mma_tf32(curO[nc], aP[ks], bfr);
                    }
                }
            } // chunks

            // finalize softmax row sums across quad
            l0 += __shfl_xor_sync(0xffffffffu, l0, 1);
            l0 += __shfl_xor_sync(0xffffffffu, l0, 2);
            l1 += __shfl_xor_sync(0xffffffffu, l1, 1);
            l1 += __shfl_xor_sync(0xffffffffu, l1, 2);
            float inv0 = 1.f / l0, inv1 = 1.f / l1;

            // acc += coef_c(t) * (1/l) * curO
            #pragma unroll
            for (int nc = 0; nc < 8; nc++) {
                int c = nc*8 + 2*lc;
                float2 cs = *(const float2*)&chS[c];
                float coef0 = cs.x, coef1 = cs.y;
                if (t == TT-1) {
                    float2 w = *(const float2*)&chW0[c];
                    coef0 -= w.x; coef1 -= w.y;
                }
                if (t == 0) {
                    float2 w = *(const float2*)&chW2[c];
                    coef0 -= w.x; coef1 -= w.y;
                }
                acc[pass][nc*4+0] += coef0*inv0*curO[nc][0];
                acc[pass][nc*4+1] += coef1*inv0*curO[nc][1];
                acc[pass][nc*4+2] += coef0*inv1*curO[nc][2];
                acc[pass][nc*4+3] += coef1*inv1*curO[nc][3];
            }
        } // pass
    } // t

    // epilogue: mix = acc + tconv_bias
    #pragma unroll
    for (int pass = 0; pass < 2; pass++) {
        int qb = pass*128 + warp*16;
        #pragma unroll
        for (int nc = 0; nc < 8; nc++) {
            int c = nc*8 + 2*lc;
            int d = h*64 + c;
            float2 tbv = *(const float2*)&tb[d];
            float* o0 = outp + (size_t)(n*QQ + qb + lr    )*DD + d;
            float* o1 = outp + (size_t)(n*QQ + qb + lr + 8)*DD + d;
            *(float2*)o0 = make_float2(acc[pass][nc*4+0] + tbv.x, acc[pass][nc*4+1] + tbv.y);
            *(float2*)o1 = make_float2(acc[pass][nc*4+2] + tbv.x, acc[pass][nc*4+3] + tbv.y);
        }
    }
}

// ---------------- launch ----------------
extern "C" void kernel_launch(void* const* d_in, const int* in_sizes, int n_in,
                              void* d_out, int out_size)
{
    const float* attrs_k = (const float*)d_in[0];
    const float* attrs_v = (const float*)d_in[1];
    const float* s       = (const float*)d_in[2];
    const float* te      = (const float*)d_in[3];
    const float* pm      = (const float*)d_in[4];
    const float* ln1w    = (const float*)d_in[5];
    const float* ln1b    = (const float*)d_in[6];
    const float* ipw     = (const float*)d_in[7];
    const float* ipb     = (const float*)d_in[8];
    const float* opw     = (const float*)d_in[9];
    const float* opb     = (const float*)d_in[10];
    const float* ln2w    = (const float*)d_in[11];
    const float* ln2b    = (const float*)d_in[12];
    const float* fcw     = (const float*)d_in[13];
    const float* fcb     = (const float*)d_in[14];
    const float* pjw     = (const float*)d_in[15];
    const float* pjb     = (const float*)d_in[16];
    const float* slnw    = (const float*)d_in[17];
    const float* slnb    = (const float*)d_in[18];
    const float* sl1     = (const float*)d_in[19];
    const float* sl2     = (const float*)d_in[20];
    const float* tlnw    = (const float*)d_in[21];
    const float* tlnb    = (const float*)d_in[22];
    const float* tl1     = (const float*)d_in[23];
    const float* tl2     = (const float*)d_in[24];
    const float* tw      = (const float*)d_in[25];
    const float* tb      = (const float*)d_in[26];
    float* out = (float*)d_out;

    float *ln_buf, *h1, *sadj, *x, *sqb, *mix, *s1, *hmid, *tek, *tev;
    cudaGetSymbolAddress((void**)&ln_buf, g_ln);
    cudaGetSymbolAddress((void**)&h1,     g_h1);
    cudaGetSymbolAddress((void**)&sadj,   g_sadj);
    cudaGetSymbolAddress((void**)&x,      g_x);
    cudaGetSymbolAddress((void**)&sqb,    g_sq);
    cudaGetSymbolAddress((void**)&mix,    g_mix);
    cudaGetSymbolAddress((void**)&s1,     g_s1);
    cudaGetSymbolAddress((void**)&hmid,   g_hmid);
    cudaGetSymbolAddress((void**)&tek,    g_tek);
    cudaGetSymbolAddress((void**)&tev,    g_tev);

    static int att_smem = ATT_SMEM_WORDS * 4;
    cudaFuncSetAttribute(att_mma, cudaFuncAttributeMaxDynamicSharedMemorySize, att_smem);

    // te path (independent, tiny)
    te_kernel<<<TT, 256>>>(te, tlnw, tlnb, tl1, tl2, ipw, ipb, tek, tev);

    // s adaptor: _s = s + (LN(s) @ l1^T) @ l2^T
    ln_rows_k<<<MROWS, 256>>>(s, slnw, slnb, ln_buf);
    tgemm<0><<<dim3(1, 16), 256>>>(ln_buf, sl1, nullptr, nullptr, h1, MROWS, 128, DD, 1.f);
    tgemm<2><<<dim3(8, 16), 256>>>(h1, sl2, nullptr, s, sadj, MROWS, DD, 128, 1.f);

    // x = LN1(_s); sq = (x @ Wq^T + bq) * (1/sqrt(C))
    ln_rows_k<<<MROWS, 256>>>(sadj, ln1w, ln1b, x);
    tgemm<1><<<dim3(8, 16), 256>>>(x, ipw, ipb, nullptr, sqb, MROWS, DD, DD, 0.125f);

    // fused attention + conv-over-t + mean-over-t (tf32 MMA)
    att_mma<<<dim3(HH, NB), 256, att_smem>>>(sqb, attrs_k, attrs_v, tek, tev, pm, tw, tb, mix);

    // s1 = s + mix @ out_proj^T + b
    tgemm<2><<<dim3(8, 16), 256>>>(mix, opw, opb, s, s1, MROWS, DD, DD, 1.f);

    // MLP
    ln_rows_k<<<MROWS, 256>>>(s1, ln2w, ln2b, x);
    tgemm<3><<<dim3(32, 16), 256>>>(x, fcw, fcb, nullptr, hmid, MROWS, 4*DD, DD, 1.f);
    tgemm<2><<<dim3(8, 16), 256>>>(hmid, pjw, pjb, s1, out, MROWS, DD, 4*DD, 1.f);
}